// round 12
// baseline (speedup 1.0000x reference)
#include <cuda_runtime.h>
#include <cuda_fp16.h>
#include <math.h>
#include <stdint.h>

#define BB 32
#define KK 8192
#define DC 256
#define DQ 256
#define HID 256
#define SK 50
#define IB 512
#define EH 512

// ---- output layout (f32, tuple concatenated) ----
#define OFF_Z    0ull
#define OFF_SEL  819200ull
#define OFF_KL   13926400ull
#define OFF_HARD 13926401ull
#define OFF_SSC  27033601ull
#define OFF_SRS  27035201ull

// ---- scratch ----
__device__ float g_logits[BB * KK];
__device__ float g_sel[BB * KK];
__device__ float g_qW1[BB * HID];
__device__ float g_qWe1[BB * EH];
__device__ int   g_topk[BB * SK];
// W1^T fp16 fragment-permuted (for logits): 8 chunks(32k) x 1024 uint4
__device__ __align__(16) uint4 g_Bp[8 * 1024];
// We1^T fp16 fragment-permuted: 131072 halves
__device__ __align__(16) __half g_We1p[131072];
// We2^T fp16 fragment-permuted + mu/ls column interleave: 524288 halves
__device__ __align__(16) __half g_We2p[524288];

// ===================== helpers =====================
__device__ __forceinline__ uint32_t h2u(__half2 h) {
    return *reinterpret_cast<uint32_t*>(&h);
}
__device__ __forceinline__ uint32_t smem_u32(const void* p) {
    uint32_t a;
    asm("{ .reg .u64 t; cvta.to.shared.u64 t, %1; cvt.u32.u64 %0, t; }" : "=r"(a) : "l"(p));
    return a;
}
__device__ __forceinline__ void mma16(float* c, const uint4& a, uint32_t b0, uint32_t b1) {
    asm volatile(
        "mma.sync.aligned.m16n8k16.row.col.f32.f16.f16.f32 "
        "{%0,%1,%2,%3},{%4,%5,%6,%7},{%8,%9},{%0,%1,%2,%3};"
        : "+f"(c[0]), "+f"(c[1]), "+f"(c[2]), "+f"(c[3])
        : "r"(a.x), "r"(a.y), "r"(a.z), "r"(a.w), "r"(b0), "r"(b1));
}
__device__ __forceinline__ void cp16(uint32_t dst, const void* src) {
    asm volatile("cp.async.cg.shared.global [%0], [%1], 16;" :: "r"(dst), "l"(src));
}
#define CP_COMMIT() asm volatile("cp.async.commit_group;" ::: "memory")
#define CP_WAIT0()  asm volatile("cp.async.wait_group 0;" ::: "memory")

// A-fragment load from row-major fp16 smem (stride in halves)
__device__ __forceinline__ uint4 ldsA(const __half* A, int stride, int rb, int kb, int lane) {
    const __half* p0 = A + (rb + (lane >> 2)) * stride + kb + (lane & 3) * 2;
    uint4 a;
    a.x = *reinterpret_cast<const uint32_t*>(p0);
    a.y = *reinterpret_cast<const uint32_t*>(p0 + 8 * stride);
    a.z = *reinterpret_cast<const uint32_t*>(p0 + 8);
    a.w = *reinterpret_cast<const uint32_t*>(p0 + 8 * stride + 8);
    return a;
}
// B-fragment direct from permuted gmem: frag = 128 halves, lane owns 4
__device__ __forceinline__ uint2 ldgB(const __half* __restrict__ base,
                                      int fragIdx, int lane) {
    return *reinterpret_cast<const uint2*>(base + (size_t)fragIdx * 128 + lane * 4);
}

// ===================== prep: W1 permute + qproj only =====================
__global__ void __launch_bounds__(256)
prep_kernel(const float* __restrict__ W1,
            const float* __restrict__ q,
            const float* __restrict__ We1) {
    int blk = blockIdx.x, tid = threadIdx.x;
    if (blk < 256) {   // W1 -> permuted fp16 fragments for logits
        int idx = blk * 256 + tid;
        int k = idx >> 8, n2 = idx & 255;
        float x = W1[(size_t)k * HID + n2];
        int c = k >> 5, kp = k & 31;
        int ntile = n2 >> 3, g = n2 & 7;
        int ktile = kp >> 4;
        int lane = g * 4 + ((kp & 7) >> 1);
        int pos = (kp & 1) + 2 * ((kp & 15) >> 3);
        size_t off = (size_t)c * 8192 +
                     (size_t)(((ntile * 2 + ktile) * 32 + lane) * 4 + pos);
        reinterpret_cast<__half*>(g_Bp)[off] = __float2half_rn(x);
        return;
    }
    blk -= 256;        // qproj: 3 per batch (96 blocks)
    int sub = blk % 3, b = blk / 3;
    __shared__ float qs[DQ];
    qs[tid] = q[b * DQ + tid];
    __syncthreads();
    float s = 0.f;
    if (sub == 0) {
        #pragma unroll 8
        for (int d = 0; d < DQ; d++) s += qs[d] * W1[(size_t)(DC + d) * HID + tid];
        g_qW1[b * HID + tid] = s;
    } else {
        int c0 = (sub - 1) * 256 + tid;
        #pragma unroll 8
        for (int d = 0; d < DQ; d++) s += qs[d] * We1[(size_t)(DC + d) * EH + c0];
        g_qWe1[b * EH + c0] = s;
    }
}

// ===================== scorer logits: fp16 1-pass, depth-2 A prefetch =====================
#define SAH 0
#define SB  8192
#define STAGE_B 40960
#define SM_DYN (2 * STAGE_B)

struct PrefA { float4 a[4]; };

__device__ __forceinline__ void load_prefA(PrefA& p, const float* __restrict__ cand,
                                           int b, int k0, int c, int tid) {
    #pragma unroll
    for (int t = 0; t < 4; t++) {
        int idx = tid + t * 256;
        int m = idx >> 4, k4 = idx & 15;
        p.a[t] = *reinterpret_cast<const float4*>(
            &cand[((size_t)b * KK + k0 + m) * DC + c * 64 + k4 * 4]);
    }
}

__device__ __forceinline__ void cp_asyncB(uint32_t stb, int c, int tid) {
    #pragma unroll
    for (int t = 0; t < 8; t++) {
        int idx = tid + t * 256;
        int sub = idx >> 10, j = idx & 1023;
        cp16(stb + SB + sub * 16384 + j * 16, &g_Bp[(c * 2 + sub) * 1024 + j]);
    }
}

__device__ __forceinline__ void store_stageA(char* __restrict__ st, const PrefA& p, int tid) {
    #pragma unroll
    for (int t = 0; t < 4; t++) {
        int idx = tid + t * 256;
        int m = idx >> 4, k4 = idx & 15;
        int sub = k4 >> 3, k4in = k4 & 7;
        float4 v = p.a[t];
        uint32_t h01 = h2u(__floats2half2_rn(v.x, v.y));
        uint32_t h23 = h2u(__floats2half2_rn(v.z, v.w));
        int mtile = m >> 4, r = m & 15;
        int ktile = k4in >> 2;
        int lane0 = (r & 7) * 4 + (k4in & 1) * 2;
        int boff = 2 * ((r >> 3) & 1) + 4 * ((k4in >> 1) & 1);
        int base = sub * 4096 + ((mtile * 2 + ktile) * 32) * 16 + boff * 2;
        *reinterpret_cast<uint32_t*>(st + SAH + base + lane0 * 16)       = h01;
        *reinterpret_cast<uint32_t*>(st + SAH + base + (lane0 + 1) * 16) = h23;
    }
}

__device__ __forceinline__ void compute_sub(const char* __restrict__ st, int sub,
                                            float acc[2][8][4],
                                            int wm, int wn, int lane) {
    #pragma unroll
    for (int kt = 0; kt < 2; kt++) {
        uint4 ah[2];
        #pragma unroll
        for (int mt = 0; mt < 2; mt++) {
            int off = sub * 4096 + (((wm * 2 + mt) * 2 + kt) * 32 + lane) * 16;
            ah[mt] = *reinterpret_cast<const uint4*>(st + SAH + off);
        }
        #pragma unroll
        for (int nt = 0; nt < 8; nt++) {
            int ntile = wn * 8 + nt;
            int boff = sub * 16384 + ((ntile * 2 + kt) * 32 + lane) * 8;
            uint2 bb = *reinterpret_cast<const uint2*>(st + SB + boff);
            #pragma unroll
            for (int mt = 0; mt < 2; mt++)
                mma16(acc[mt][nt], ah[mt], bb.x, bb.y);
        }
    }
}

__global__ void __launch_bounds__(256, 2)
logits_mma_kernel(const float* __restrict__ cand,
                  const float* __restrict__ b1,
                  const float* __restrict__ W2,
                  const float* __restrict__ b2,
                  const float* __restrict__ gum,
                  const float* __restrict__ We1,
                  const float* __restrict__ We2,
                  float* __restrict__ out) {
    extern __shared__ char dsm[];
    __shared__ float qb_s[HID];
    __shared__ float w2_s[HID];
    __shared__ float part[64][4];

    const int tid = threadIdx.x;
    const int b = blockIdx.y;
    const int k0 = blockIdx.x * 64;
    const int w = tid >> 5, lane = tid & 31;
    const int wm = w & 1, wn = w >> 1;
    const uint32_t sb = smem_u32(dsm);
    const int bid = blockIdx.y * gridDim.x + blockIdx.x;    // 0..4095

    // ---- fused: zero SEL+KL+HARD, permute We1/We2 slices (160 elems/block) ----
    {
        float4* oz = reinterpret_cast<float4*>(out) + 204800 + (size_t)bid * 1600;
        float4 z4 = make_float4(0.f, 0.f, 0.f, 0.f);
        #pragma unroll
        for (int t = tid; t < 1600; t += 256) oz[t] = z4;
        if (bid == 0 && tid == 0) out[27033600] = 0.f;
        if (tid < 160) {
            int e = bid * 160 + tid;                        // 0..655359
            if (e < 131072) {
                int k = e >> 9, n2 = e & 511;
                float x = We1[(size_t)k * EH + n2];
                int c = k >> 5, kp = k & 31;
                int ntile = n2 >> 3, g = n2 & 7;
                int ktile = kp >> 4;
                int ln = g * 4 + ((kp & 7) >> 1);
                int pos = (kp & 1) + 2 * ((kp & 15) >> 3);
                g_We1p[(((c * 64 + ntile) * 2 + ktile) * 32 + ln) * 4 + pos] =
                    __float2half_rn(x);
            } else {
                int e2 = e - 131072;
                int k = e2 >> 10, n2 = e2 & 1023;
                float x = We2[(size_t)k * (2 * IB) + n2];
                int pcol = (n2 < 512) ? (2 * n2) : (2 * (n2 - 512) + 1);
                int c = k >> 5, kp = k & 31;
                int ntile = pcol >> 3, g = pcol & 7;
                int ktile = kp >> 4;
                int ln = g * 4 + ((kp & 7) >> 1);
                int pos = (kp & 1) + 2 * ((kp & 15) >> 3);
                g_We2p[(((c * 128 + ntile) * 2 + ktile) * 32 + ln) * 4 + pos] =
                    __float2half_rn(x);
            }
        }
    }

    qb_s[tid] = g_qW1[b * HID + tid] + b1[tid];
    w2_s[tid] = W2[tid];

    float acc[2][8][4];
    #pragma unroll
    for (int mt = 0; mt < 2; mt++)
        #pragma unroll
        for (int nt = 0; nt < 8; nt++)
            #pragma unroll
            for (int r = 0; r < 4; r++) acc[mt][nt][r] = 0.f;

    // prologue: A depth-2 register prefetch; B double-buffered cp.async
    PrefA pA[2];
    load_prefA(pA[0], cand, b, k0, 0, tid);
    cp_asyncB(sb, 0, tid);
    CP_COMMIT();
    store_stageA(dsm, pA[0], tid);
    load_prefA(pA[1], cand, b, k0, 1, tid);     // chunk 1, full-iter latency cover
    CP_WAIT0();
    __syncthreads();

    #pragma unroll
    for (int c = 0; c < 4; c++) {
        if (c < 2) load_prefA(pA[c & 1], cand, b, k0, c + 2, tid);  // chunk c+2
        if (c < 3) { cp_asyncB(sb + ((c + 1) & 1) * STAGE_B, c + 1, tid); CP_COMMIT(); }
        compute_sub(dsm + (c & 1) * STAGE_B, 0, acc, wm, wn, lane);
        if (c < 3) store_stageA(dsm + ((c + 1) & 1) * STAGE_B, pA[(c + 1) & 1], tid);
        compute_sub(dsm + (c & 1) * STAGE_B, 1, acc, wm, wn, lane);
        CP_WAIT0();
        __syncthreads();
    }

    float rs[2][2] = {{0.f, 0.f}, {0.f, 0.f}};
    #pragma unroll
    for (int mt = 0; mt < 2; mt++)
        #pragma unroll
        for (int nt = 0; nt < 8; nt++)
            #pragma unroll
            for (int ci = 0; ci < 4; ci++) {
                int col = wn * 64 + nt * 8 + (lane & 3) * 2 + (ci & 1);
                float v = acc[mt][nt][ci] + qb_s[col];
                rs[mt][ci >> 1] += fmaxf(v, 0.f) * w2_s[col];
            }
    #pragma unroll
    for (int mt = 0; mt < 2; mt++)
        #pragma unroll
        for (int rh = 0; rh < 2; rh++) {
            float s = rs[mt][rh];
            s += __shfl_xor_sync(0xffffffffu, s, 1);
            s += __shfl_xor_sync(0xffffffffu, s, 2);
            if ((lane & 3) == 0)
                part[wm * 32 + mt * 16 + rh * 8 + (lane >> 2)][wn] = s;
        }
    __syncthreads();
    if (tid < 64) {
        float lg = part[tid][0] + part[tid][1] + part[tid][2] + part[tid][3] + b2[0];
        size_t gi = (size_t)b * KK + k0 + tid;
        g_logits[gi] = lg;
        g_sel[gi] = lg + gum[gi];
    }
}

// ===================== top-k via 4-level radix select =====================
__global__ void __launch_bounds__(1024)
topk_kernel(const float* __restrict__ cand_score, float* __restrict__ out) {
    const int b = blockIdx.x;
    const int tid = threadIdx.x;
    const int base = tid * 8;

    __shared__ uint32_t hist8[8][256];
    __shared__ uint32_t shist[256];
    __shared__ uint32_t s_prefix, s_above;
    __shared__ uint32_t cntG, cntE;
    __shared__ uint32_t gk[64];
    __shared__ int      gi[64];
    __shared__ int      ei[256];

    uint32_t k[8];
    #pragma unroll
    for (int r = 0; r < 8; r++) {
        uint32_t u = __float_as_uint(g_sel[(size_t)b * KK + base + r]);
        k[r] = (u & 0x80000000u) ? ~u : (u | 0x80000000u);
    }
    if (tid == 0) { s_prefix = 0; s_above = 0; cntG = 0; cntE = 0; }

    #pragma unroll
    for (int round = 0; round < 4; round++) {
        const int shift = 24 - round * 8;
        if (round == 0) {
            #pragma unroll
            for (int t = 0; t < 2; t++) hist8[(tid + t * 1024) >> 8][(tid + t * 1024) & 255] = 0;
        } else if (tid < 256) shist[tid] = 0;
        __syncthreads();
        uint32_t pfx = s_prefix;
        if (round == 0) {
            uint32_t* hh = hist8[(tid >> 5) & 7];
            #pragma unroll
            for (int r = 0; r < 8; r++) atomicAdd(&hh[k[r] >> 24], 1u);
        } else {
            const int ps = shift + 8;
            #pragma unroll
            for (int r = 0; r < 8; r++)
                if ((k[r] >> ps) == (pfx >> ps))
                    atomicAdd(&shist[(k[r] >> shift) & 255u], 1u);
        }
        __syncthreads();
        if (round == 0 && tid < 256) {
            uint32_t s = 0;
            #pragma unroll
            for (int g = 0; g < 8; g++) s += hist8[g][tid];
            shist[tid] = s;
        }
        if (round == 0) __syncthreads();
        if (tid < 32) {
            uint32_t loc[8], tot = 0;
            #pragma unroll
            for (int j = 0; j < 8; j++) { loc[j] = shist[tid * 8 + j]; tot += loc[j]; }
            uint32_t suf = tot;
            #pragma unroll
            for (int off = 1; off < 32; off <<= 1) {
                uint32_t v = __shfl_down_sync(0xffffffffu, suf, off);
                if (tid + off < 32) suf += v;
            }
            uint32_t exclHi = suf - tot;
            uint32_t target = 50u - s_above;
            bool has = (exclHi < target) && (exclHi + tot >= target);
            if (has) {
                uint32_t c = exclHi;
                #pragma unroll
                for (int j = 7; j >= 0; j--) {
                    uint32_t nc = c + loc[j];
                    if (nc >= target) {
                        s_prefix = pfx | ((uint32_t)(tid * 8 + j) << shift);
                        s_above += c;
                        break;
                    }
                    c = nc;
                }
            }
        }
        __syncthreads();
    }

    const uint32_t T50 = s_prefix;
    const uint32_t C1 = s_above;
    const int E = 50 - (int)C1;

    #pragma unroll
    for (int r = 0; r < 8; r++) {
        if (k[r] > T50) {
            uint32_t pos = atomicAdd(&cntG, 1u);
            gk[pos] = k[r]; gi[pos] = base + r;
        } else if (k[r] == T50) {
            uint32_t pos = atomicAdd(&cntE, 1u);
            if (pos < 256) ei[pos] = base + r;
        }
    }
    __syncthreads();

    if (tid < (int)C1) {
        uint32_t mk = gk[tid]; int mi = gi[tid];
        int rank = 0;
        for (int j = 0; j < (int)C1; j++)
            if (gk[j] > mk || (gk[j] == mk && gi[j] < mi)) rank++;
        int row = b * SK + rank;
        g_topk[row] = mi;
        out[OFF_SSC + row] = g_logits[(size_t)b * KK + mi];
        out[OFF_SRS + row] = cand_score[(size_t)b * KK + mi];
        out[OFF_SEL + (size_t)row * KK + mi] = 1.0f;
        out[OFF_HARD + (size_t)row * KK + mi] = 1.0f;
    }
    int nE = (int)cntE; if (nE > 256) nE = 256;
    if (tid < nE) {
        int mi = ei[tid];
        int rank = 0;
        for (int j = 0; j < nE; j++) if (ei[j] < mi) rank++;
        if (rank < E) {
            int row = b * SK + (int)C1 + rank;
            g_topk[row] = mi;
            out[OFF_SSC + row] = g_logits[(size_t)b * KK + mi];
            out[OFF_SRS + row] = cand_score[(size_t)b * KK + mi];
            out[OFF_SEL + (size_t)row * KK + mi] = 1.0f;
            out[OFF_HARD + (size_t)row * KK + mi] = 1.0f;
        }
    }
}

// ===================== encoder: fp16 TC, 512 thr, grid(8,BB), B direct gmem =====================
#define EST 264            // A1 row stride (halves)
#define HST 520            // HE row stride (halves)
#define O_A1 0
#define O_HE 33792
#define O_QB 100352
#define O_BE2 102400
#define ENC_SMEM 106496

__global__ void __launch_bounds__(512, 2)
encoder_kernel(const float* __restrict__ cand,
               const float* __restrict__ be1,
               const float* __restrict__ be2,
               const float* __restrict__ eps,
               float* __restrict__ out) {
    extern __shared__ char esm[];
    __half* A1  = reinterpret_cast<__half*>(esm + O_A1);
    __half* HE  = reinterpret_cast<__half*>(esm + O_HE);
    float* qb1  = reinterpret_cast<float*>(esm + O_QB);
    float* be2s = reinterpret_cast<float*>(esm + O_BE2);
    __shared__ int idxs[64];
    __shared__ float redp[16];

    const int tid = threadIdx.x;
    const int b = blockIdx.y;
    const int bx = blockIdx.x;              // N-eighth of GEMM2
    const int w = tid >> 5, lane = tid & 31;
    const int wm = w & 1, wn = w >> 1;      // wn 0..7

    if (tid < 64) idxs[tid] = (tid < 50) ? g_topk[b * SK + tid] : 0;
    qb1[tid]  = g_qWe1[b * EH + tid] + be1[tid];
    be2s[tid]       = be2[tid];
    be2s[tid + 512] = be2[tid + 512];
    __syncthreads();

    // gather selected rows -> A1 fp16 (rows 50..63 zero)
    #pragma unroll
    for (int t = 0; t < 8; t++) {
        int idx = tid + t * 512;
        int r = idx >> 6, k4 = idx & 63;
        uint2 u; u.x = 0u; u.y = 0u;
        if (r < 50) {
            float4 v = *reinterpret_cast<const float4*>(
                &cand[((size_t)b * KK + idxs[r]) * DC + k4 * 4]);
            u.x = h2u(__floats2half2_rn(v.x, v.y));
            u.y = h2u(__floats2half2_rn(v.z, v.w));
        }
        *reinterpret_cast<uint2*>(&A1[r * EST + k4 * 4]) = u;
    }
    __syncthreads();

    // ---- GEMM1: full 512 cols across 8 wn (redundant over bx) ----
    {
        float acc[2][8][4];
        #pragma unroll
        for (int mt = 0; mt < 2; mt++)
            #pragma unroll
            for (int nt = 0; nt < 8; nt++)
                #pragma unroll
                for (int r = 0; r < 4; r++) acc[mt][nt][r] = 0.f;

        #pragma unroll 4
        for (int kt = 0; kt < 16; kt++) {
            int c = kt >> 1, ktile = kt & 1;
            uint4 a[2];
            #pragma unroll
            for (int mt = 0; mt < 2; mt++)
                a[mt] = ldsA(A1, EST, wm * 32 + mt * 16, kt * 16, lane);
            #pragma unroll
            for (int nt = 0; nt < 8; nt++) {
                int ntl = wn * 8 + nt;
                uint2 bb = ldgB(g_We1p, (c * 64 + ntl) * 2 + ktile, lane);
                #pragma unroll
                for (int mt = 0; mt < 2; mt++)
                    mma16(acc[mt][nt], a[mt], bb.x, bb.y);
            }
        }
        // epilogue -> HE fp16
        #pragma unroll
        for (int mt = 0; mt < 2; mt++)
            #pragma unroll
            for (int nt = 0; nt < 8; nt++)
                #pragma unroll
                for (int pp = 0; pp < 2; pp++) {
                    int col = wn * 64 + nt * 8 + (lane & 3) * 2;
                    int row = wm * 32 + mt * 16 + (lane >> 2) + 8 * pp;
                    float v0 = fmaxf(acc[mt][nt][2 * pp]     + qb1[col],     0.f);
                    float v1 = fmaxf(acc[mt][nt][2 * pp + 1] + qb1[col + 1], 0.f);
                    *reinterpret_cast<uint32_t*>(&HE[row * HST + col]) =
                        h2u(__floats2half2_rn(v0, v1));
                }
    }
    __syncthreads();   // HE exchange

    // ---- GEMM2: N-eighth bx, 16 ntiles over 8 wn (2 each) ----
    float acc2[2][2][4];
    #pragma unroll
    for (int mt = 0; mt < 2; mt++)
        #pragma unroll
        for (int nt = 0; nt < 2; nt++)
            #pragma unroll
            for (int r = 0; r < 4; r++) acc2[mt][nt][r] = 0.f;

    #pragma unroll 8
    for (int kt = 0; kt < 32; kt++) {
        int c = kt >> 1, ktile = kt & 1;
        uint4 a[2];
        #pragma unroll
        for (int mt = 0; mt < 2; mt++)
            a[mt] = ldsA(HE, HST, wm * 32 + mt * 16, kt * 16, lane);
        #pragma unroll
        for (int nt = 0; nt < 2; nt++) {
            int ntl = bx * 16 + wn * 2 + nt;
            uint2 bb = ldgB(g_We2p, (c * 128 + ntl) * 2 + ktile, lane);
            #pragma unroll
            for (int mt = 0; mt < 2; mt++)
                mma16(acc2[mt][nt], a[mt], bb.x, bb.y);
        }
    }

    // epilogue: (mu, ls) pairs -> z, kl
    float kl = 0.f;
    #pragma unroll
    for (int mt = 0; mt < 2; mt++)
        #pragma unroll
        for (int nt = 0; nt < 2; nt++)
            #pragma unroll
            for (int pp = 0; pp < 2; pp++) {
                int j = (bx * 16 + wn * 2 + nt) * 4 + (lane & 3);
                int row = wm * 32 + mt * 16 + (lane >> 2) + 8 * pp;
                if (row < 50) {
                    float mu  = acc2[mt][nt][2 * pp]     + be2s[j];
                    float lsr = acc2[mt][nt][2 * pp + 1] + be2s[512 + j];
                    float lsc = fminf(fmaxf(lsr, -10.f), 10.f);
                    float sd = expf(lsc);
                    size_t grow = (size_t)b * SK + row;
                    out[OFF_Z + grow * IB + j] = mu + sd * eps[grow * IB + j];
                    kl += mu * mu + sd * sd - 1.0f - 2.0f * lsr;
                }
            }
    #pragma unroll
    for (int off = 16; off; off >>= 1) kl += __shfl_down_sync(0xffffffffu, kl, off);
    if (lane == 0) redp[w] = kl;
    __syncthreads();
    if (tid == 0) {
        float s = 0.f;
        #pragma unroll
        for (int ww = 0; ww < 16; ww++) s += redp[ww];
        atomicAdd(&out[OFF_KL], 0.5f * s * (0.001f / (float)(BB * SK)));
    }
}

// ===================== launch =====================
extern "C" void kernel_launch(void* const* d_in, const int* in_sizes, int n_in,
                              void* d_out, int out_size) {
    const float* query = (const float*)d_in[0];
    const float* cand  = (const float*)d_in[1];
    const float* score = (const float*)d_in[2];
    const float* gum   = (const float*)d_in[3];
    const float* eps   = (const float*)d_in[4];
    const float* W1    = (const float*)d_in[5];
    const float* b1    = (const float*)d_in[6];
    const float* W2    = (const float*)d_in[7];
    const float* b2    = (const float*)d_in[8];
    const float* We1   = (const float*)d_in[9];
    const float* be1   = (const float*)d_in[10];
    const float* We2   = (const float*)d_in[11];
    const float* be2   = (const float*)d_in[12];
    float* out = (float*)d_out;

    static int attr_set = 0;
    if (!attr_set) {
        cudaFuncSetAttribute(logits_mma_kernel,
                             cudaFuncAttributeMaxDynamicSharedMemorySize, SM_DYN);
        cudaFuncSetAttribute(encoder_kernel,
                             cudaFuncAttributeMaxDynamicSharedMemorySize, ENC_SMEM);
        attr_set = 1;
    }

    prep_kernel<<<256 + 96, 256>>>(W1, query, We1);
    logits_mma_kernel<<<dim3(KK / 64, BB), 256, SM_DYN>>>(cand, b1, W2, b2, gum,
                                                          We1, We2, out);
    topk_kernel<<<BB, 1024>>>(score, out);
    encoder_kernel<<<dim3(8, BB), 512, ENC_SMEM>>>(cand, be1, be2, eps, out);
}

// round 13
// speedup vs baseline: 1.3521x; 1.3521x over previous
#include <cuda_runtime.h>
#include <cuda_fp16.h>
#include <math.h>
#include <stdint.h>

#define BB 32
#define KK 8192
#define DC 256
#define DQ 256
#define HID 256
#define SK 50
#define IB 512
#define EH 512

// ---- output layout (f32, tuple concatenated) ----
#define OFF_Z    0ull
#define OFF_SEL  819200ull
#define OFF_KL   13926400ull
#define OFF_HARD 13926401ull
#define OFF_SSC  27033601ull
#define OFF_SRS  27035201ull

// ---- scratch ----
__device__ float g_logits[BB * KK];
__device__ float g_sel[BB * KK];
__device__ float g_qW1[BB * HID];
__device__ float g_qWe1[BB * EH];
__device__ int   g_topk[BB * SK];
// W1^T fp16 fragment-permuted (for logits): 8 chunks(32k) x 1024 uint4
__device__ __align__(16) uint4 g_Bp[8 * 1024];
// We1^T fp16 fragment-permuted: 131072 halves
__device__ __align__(16) __half g_We1p[131072];
// We2^T fp16 fragment-permuted + mu/ls column interleave: 524288 halves
__device__ __align__(16) __half g_We2p[524288];

// ===================== helpers =====================
__device__ __forceinline__ uint32_t h2u(__half2 h) {
    return *reinterpret_cast<uint32_t*>(&h);
}
__device__ __forceinline__ uint32_t smem_u32(const void* p) {
    uint32_t a;
    asm("{ .reg .u64 t; cvta.to.shared.u64 t, %1; cvt.u32.u64 %0, t; }" : "=r"(a) : "l"(p));
    return a;
}
__device__ __forceinline__ void mma16(float* c, const uint4& a, uint32_t b0, uint32_t b1) {
    asm volatile(
        "mma.sync.aligned.m16n8k16.row.col.f32.f16.f16.f32 "
        "{%0,%1,%2,%3},{%4,%5,%6,%7},{%8,%9},{%0,%1,%2,%3};"
        : "+f"(c[0]), "+f"(c[1]), "+f"(c[2]), "+f"(c[3])
        : "r"(a.x), "r"(a.y), "r"(a.z), "r"(a.w), "r"(b0), "r"(b1));
}
__device__ __forceinline__ void cp16(uint32_t dst, const void* src) {
    asm volatile("cp.async.cg.shared.global [%0], [%1], 16;" :: "r"(dst), "l"(src));
}
#define CP_COMMIT() asm volatile("cp.async.commit_group;" ::: "memory")
#define CP_WAIT0()  asm volatile("cp.async.wait_group 0;" ::: "memory")

// A-fragment load from row-major fp16 smem (stride in halves)
__device__ __forceinline__ uint4 ldsA(const __half* A, int stride, int rb, int kb, int lane) {
    const __half* p0 = A + (rb + (lane >> 2)) * stride + kb + (lane & 3) * 2;
    uint4 a;
    a.x = *reinterpret_cast<const uint32_t*>(p0);
    a.y = *reinterpret_cast<const uint32_t*>(p0 + 8 * stride);
    a.z = *reinterpret_cast<const uint32_t*>(p0 + 8);
    a.w = *reinterpret_cast<const uint32_t*>(p0 + 8 * stride + 8);
    return a;
}
// B-fragment direct from permuted gmem: frag = 128 halves, lane owns 4
__device__ __forceinline__ uint2 ldgB(const __half* __restrict__ base,
                                      int fragIdx, int lane) {
    return *reinterpret_cast<const uint2*>(base + (size_t)fragIdx * 128 + lane * 4);
}

// ===================== prep: W1 permute + qproj only =====================
__global__ void __launch_bounds__(256)
prep_kernel(const float* __restrict__ W1,
            const float* __restrict__ q,
            const float* __restrict__ We1) {
    int blk = blockIdx.x, tid = threadIdx.x;
    if (blk < 256) {   // W1 -> permuted fp16 fragments for logits
        int idx = blk * 256 + tid;
        int k = idx >> 8, n2 = idx & 255;
        float x = W1[(size_t)k * HID + n2];
        int c = k >> 5, kp = k & 31;
        int ntile = n2 >> 3, g = n2 & 7;
        int ktile = kp >> 4;
        int lane = g * 4 + ((kp & 7) >> 1);
        int pos = (kp & 1) + 2 * ((kp & 15) >> 3);
        size_t off = (size_t)c * 8192 +
                     (size_t)(((ntile * 2 + ktile) * 32 + lane) * 4 + pos);
        reinterpret_cast<__half*>(g_Bp)[off] = __float2half_rn(x);
        return;
    }
    blk -= 256;        // qproj: 3 per batch (96 blocks)
    int sub = blk % 3, b = blk / 3;
    __shared__ float qs[DQ];
    qs[tid] = q[b * DQ + tid];
    __syncthreads();
    float s = 0.f;
    if (sub == 0) {
        #pragma unroll 8
        for (int d = 0; d < DQ; d++) s += qs[d] * W1[(size_t)(DC + d) * HID + tid];
        g_qW1[b * HID + tid] = s;
    } else {
        int c0 = (sub - 1) * 256 + tid;
        #pragma unroll 8
        for (int d = 0; d < DQ; d++) s += qs[d] * We1[(size_t)(DC + d) * EH + c0];
        g_qWe1[b * EH + c0] = s;
    }
}

// ===================== scorer logits: fp16 1-pass, depth-2 A prefetch =====================
#define SAH 0
#define SB  8192
#define STAGE_B 40960
#define SM_DYN (2 * STAGE_B)

struct PrefA { float4 a[4]; };

__device__ __forceinline__ void load_prefA(PrefA& p, const float* __restrict__ cand,
                                           int b, int k0, int c, int tid) {
    #pragma unroll
    for (int t = 0; t < 4; t++) {
        int idx = tid + t * 256;
        int m = idx >> 4, k4 = idx & 15;
        p.a[t] = *reinterpret_cast<const float4*>(
            &cand[((size_t)b * KK + k0 + m) * DC + c * 64 + k4 * 4]);
    }
}

__device__ __forceinline__ void cp_asyncB(uint32_t stb, int c, int tid) {
    #pragma unroll
    for (int t = 0; t < 8; t++) {
        int idx = tid + t * 256;
        int sub = idx >> 10, j = idx & 1023;
        cp16(stb + SB + sub * 16384 + j * 16, &g_Bp[(c * 2 + sub) * 1024 + j]);
    }
}

__device__ __forceinline__ void store_stageA(char* __restrict__ st, const PrefA& p, int tid) {
    #pragma unroll
    for (int t = 0; t < 4; t++) {
        int idx = tid + t * 256;
        int m = idx >> 4, k4 = idx & 15;
        int sub = k4 >> 3, k4in = k4 & 7;
        float4 v = p.a[t];
        uint32_t h01 = h2u(__floats2half2_rn(v.x, v.y));
        uint32_t h23 = h2u(__floats2half2_rn(v.z, v.w));
        int mtile = m >> 4, r = m & 15;
        int ktile = k4in >> 2;
        int lane0 = (r & 7) * 4 + (k4in & 1) * 2;
        int boff = 2 * ((r >> 3) & 1) + 4 * ((k4in >> 1) & 1);
        int base = sub * 4096 + ((mtile * 2 + ktile) * 32) * 16 + boff * 2;
        *reinterpret_cast<uint32_t*>(st + SAH + base + lane0 * 16)       = h01;
        *reinterpret_cast<uint32_t*>(st + SAH + base + (lane0 + 1) * 16) = h23;
    }
}

__device__ __forceinline__ void compute_sub(const char* __restrict__ st, int sub,
                                            float acc[2][8][4],
                                            int wm, int wn, int lane) {
    #pragma unroll
    for (int kt = 0; kt < 2; kt++) {
        uint4 ah[2];
        #pragma unroll
        for (int mt = 0; mt < 2; mt++) {
            int off = sub * 4096 + (((wm * 2 + mt) * 2 + kt) * 32 + lane) * 16;
            ah[mt] = *reinterpret_cast<const uint4*>(st + SAH + off);
        }
        #pragma unroll
        for (int nt = 0; nt < 8; nt++) {
            int ntile = wn * 8 + nt;
            int boff = sub * 16384 + ((ntile * 2 + kt) * 32 + lane) * 8;
            uint2 bb = *reinterpret_cast<const uint2*>(st + SB + boff);
            #pragma unroll
            for (int mt = 0; mt < 2; mt++)
                mma16(acc[mt][nt], ah[mt], bb.x, bb.y);
        }
    }
}

__global__ void __launch_bounds__(256, 2)
logits_mma_kernel(const float* __restrict__ cand,
                  const float* __restrict__ b1,
                  const float* __restrict__ W2,
                  const float* __restrict__ b2,
                  const float* __restrict__ gum,
                  const float* __restrict__ We1,
                  const float* __restrict__ We2,
                  float* __restrict__ out) {
    extern __shared__ char dsm[];
    __shared__ float qb_s[HID];
    __shared__ float w2_s[HID];
    __shared__ float part[64][4];

    const int tid = threadIdx.x;
    const int b = blockIdx.y;
    const int k0 = blockIdx.x * 64;
    const int w = tid >> 5, lane = tid & 31;
    const int wm = w & 1, wn = w >> 1;
    const uint32_t sb = smem_u32(dsm);
    const int bid = blockIdx.y * gridDim.x + blockIdx.x;    // 0..4095

    // ---- fused: zero SEL+KL+HARD, permute We1/We2 slices (160 elems/block) ----
    {
        float4* oz = reinterpret_cast<float4*>(out) + 204800 + (size_t)bid * 1600;
        float4 z4 = make_float4(0.f, 0.f, 0.f, 0.f);
        #pragma unroll
        for (int t = tid; t < 1600; t += 256) oz[t] = z4;
        if (bid == 0 && tid == 0) out[27033600] = 0.f;
        if (tid < 160) {
            int e = bid * 160 + tid;                        // 0..655359
            if (e < 131072) {
                int k = e >> 9, n2 = e & 511;
                float x = We1[(size_t)k * EH + n2];
                int c = k >> 5, kp = k & 31;
                int ntile = n2 >> 3, g = n2 & 7;
                int ktile = kp >> 4;
                int ln = g * 4 + ((kp & 7) >> 1);
                int pos = (kp & 1) + 2 * ((kp & 15) >> 3);
                g_We1p[(((c * 64 + ntile) * 2 + ktile) * 32 + ln) * 4 + pos] =
                    __float2half_rn(x);
            } else {
                int e2 = e - 131072;
                int k = e2 >> 10, n2 = e2 & 1023;
                float x = We2[(size_t)k * (2 * IB) + n2];
                int pcol = (n2 < 512) ? (2 * n2) : (2 * (n2 - 512) + 1);
                int c = k >> 5, kp = k & 31;
                int ntile = pcol >> 3, g = pcol & 7;
                int ktile = kp >> 4;
                int ln = g * 4 + ((kp & 7) >> 1);
                int pos = (kp & 1) + 2 * ((kp & 15) >> 3);
                g_We2p[(((c * 128 + ntile) * 2 + ktile) * 32 + ln) * 4 + pos] =
                    __float2half_rn(x);
            }
        }
    }

    qb_s[tid] = g_qW1[b * HID + tid] + b1[tid];
    w2_s[tid] = W2[tid];

    float acc[2][8][4];
    #pragma unroll
    for (int mt = 0; mt < 2; mt++)
        #pragma unroll
        for (int nt = 0; nt < 8; nt++)
            #pragma unroll
            for (int r = 0; r < 4; r++) acc[mt][nt][r] = 0.f;

    // prologue: A depth-2 register prefetch; B double-buffered cp.async
    PrefA pA[2];
    load_prefA(pA[0], cand, b, k0, 0, tid);
    cp_asyncB(sb, 0, tid);
    CP_COMMIT();
    store_stageA(dsm, pA[0], tid);
    load_prefA(pA[1], cand, b, k0, 1, tid);
    CP_WAIT0();
    __syncthreads();

    #pragma unroll
    for (int c = 0; c < 4; c++) {
        if (c < 2) load_prefA(pA[c & 1], cand, b, k0, c + 2, tid);
        if (c < 3) { cp_asyncB(sb + ((c + 1) & 1) * STAGE_B, c + 1, tid); CP_COMMIT(); }
        compute_sub(dsm + (c & 1) * STAGE_B, 0, acc, wm, wn, lane);
        if (c < 3) store_stageA(dsm + ((c + 1) & 1) * STAGE_B, pA[(c + 1) & 1], tid);
        compute_sub(dsm + (c & 1) * STAGE_B, 1, acc, wm, wn, lane);
        CP_WAIT0();
        __syncthreads();
    }

    float rs[2][2] = {{0.f, 0.f}, {0.f, 0.f}};
    #pragma unroll
    for (int mt = 0; mt < 2; mt++)
        #pragma unroll
        for (int nt = 0; nt < 8; nt++)
            #pragma unroll
            for (int ci = 0; ci < 4; ci++) {
                int col = wn * 64 + nt * 8 + (lane & 3) * 2 + (ci & 1);
                float v = acc[mt][nt][ci] + qb_s[col];
                rs[mt][ci >> 1] += fmaxf(v, 0.f) * w2_s[col];
            }
    #pragma unroll
    for (int mt = 0; mt < 2; mt++)
        #pragma unroll
        for (int rh = 0; rh < 2; rh++) {
            float s = rs[mt][rh];
            s += __shfl_xor_sync(0xffffffffu, s, 1);
            s += __shfl_xor_sync(0xffffffffu, s, 2);
            if ((lane & 3) == 0)
                part[wm * 32 + mt * 16 + rh * 8 + (lane >> 2)][wn] = s;
        }
    __syncthreads();
    if (tid < 64) {
        float lg = part[tid][0] + part[tid][1] + part[tid][2] + part[tid][3] + b2[0];
        size_t gi = (size_t)b * KK + k0 + tid;
        g_logits[gi] = lg;
        g_sel[gi] = lg + gum[gi];
    }
}

// ===================== top-k via 4-level radix select =====================
__global__ void __launch_bounds__(1024)
topk_kernel(const float* __restrict__ cand_score, float* __restrict__ out) {
    const int b = blockIdx.x;
    const int tid = threadIdx.x;
    const int base = tid * 8;

    __shared__ uint32_t hist8[8][256];
    __shared__ uint32_t shist[256];
    __shared__ uint32_t s_prefix, s_above;
    __shared__ uint32_t cntG, cntE;
    __shared__ uint32_t gk[64];
    __shared__ int      gi[64];
    __shared__ int      ei[256];

    uint32_t k[8];
    #pragma unroll
    for (int r = 0; r < 8; r++) {
        uint32_t u = __float_as_uint(g_sel[(size_t)b * KK + base + r]);
        k[r] = (u & 0x80000000u) ? ~u : (u | 0x80000000u);
    }
    if (tid == 0) { s_prefix = 0; s_above = 0; cntG = 0; cntE = 0; }

    #pragma unroll
    for (int round = 0; round < 4; round++) {
        const int shift = 24 - round * 8;
        if (round == 0) {
            #pragma unroll
            for (int t = 0; t < 2; t++) hist8[(tid + t * 1024) >> 8][(tid + t * 1024) & 255] = 0;
        } else if (tid < 256) shist[tid] = 0;
        __syncthreads();
        uint32_t pfx = s_prefix;
        if (round == 0) {
            uint32_t* hh = hist8[(tid >> 5) & 7];
            #pragma unroll
            for (int r = 0; r < 8; r++) atomicAdd(&hh[k[r] >> 24], 1u);
        } else {
            const int ps = shift + 8;
            #pragma unroll
            for (int r = 0; r < 8; r++)
                if ((k[r] >> ps) == (pfx >> ps))
                    atomicAdd(&shist[(k[r] >> shift) & 255u], 1u);
        }
        __syncthreads();
        if (round == 0 && tid < 256) {
            uint32_t s = 0;
            #pragma unroll
            for (int g = 0; g < 8; g++) s += hist8[g][tid];
            shist[tid] = s;
        }
        if (round == 0) __syncthreads();
        if (tid < 32) {
            uint32_t loc[8], tot = 0;
            #pragma unroll
            for (int j = 0; j < 8; j++) { loc[j] = shist[tid * 8 + j]; tot += loc[j]; }
            uint32_t suf = tot;
            #pragma unroll
            for (int off = 1; off < 32; off <<= 1) {
                uint32_t v = __shfl_down_sync(0xffffffffu, suf, off);
                if (tid + off < 32) suf += v;
            }
            uint32_t exclHi = suf - tot;
            uint32_t target = 50u - s_above;
            bool has = (exclHi < target) && (exclHi + tot >= target);
            if (has) {
                uint32_t c = exclHi;
                #pragma unroll
                for (int j = 7; j >= 0; j--) {
                    uint32_t nc = c + loc[j];
                    if (nc >= target) {
                        s_prefix = pfx | ((uint32_t)(tid * 8 + j) << shift);
                        s_above += c;
                        break;
                    }
                    c = nc;
                }
            }
        }
        __syncthreads();
    }

    const uint32_t T50 = s_prefix;
    const uint32_t C1 = s_above;
    const int E = 50 - (int)C1;

    #pragma unroll
    for (int r = 0; r < 8; r++) {
        if (k[r] > T50) {
            uint32_t pos = atomicAdd(&cntG, 1u);
            gk[pos] = k[r]; gi[pos] = base + r;
        } else if (k[r] == T50) {
            uint32_t pos = atomicAdd(&cntE, 1u);
            if (pos < 256) ei[pos] = base + r;
        }
    }
    __syncthreads();

    if (tid < (int)C1) {
        uint32_t mk = gk[tid]; int mi = gi[tid];
        int rank = 0;
        for (int j = 0; j < (int)C1; j++)
            if (gk[j] > mk || (gk[j] == mk && gi[j] < mi)) rank++;
        int row = b * SK + rank;
        g_topk[row] = mi;
        out[OFF_SSC + row] = g_logits[(size_t)b * KK + mi];
        out[OFF_SRS + row] = cand_score[(size_t)b * KK + mi];
        out[OFF_SEL + (size_t)row * KK + mi] = 1.0f;
        out[OFF_HARD + (size_t)row * KK + mi] = 1.0f;
    }
    int nE = (int)cntE; if (nE > 256) nE = 256;
    if (tid < nE) {
        int mi = ei[tid];
        int rank = 0;
        for (int j = 0; j < nE; j++) if (ei[j] < mi) rank++;
        if (rank < E) {
            int row = b * SK + (int)C1 + rank;
            g_topk[row] = mi;
            out[OFF_SSC + row] = g_logits[(size_t)b * KK + mi];
            out[OFF_SRS + row] = cand_score[(size_t)b * KK + mi];
            out[OFF_SEL + (size_t)row * KK + mi] = 1.0f;
            out[OFF_HARD + (size_t)row * KK + mi] = 1.0f;
        }
    }
}

// ===================== encoder: fp16 TC, M-split grid(4,BB), no redundancy =====================
#define EST 264            // A1 row stride (halves)
#define HST 520            // HE row stride (halves)
#define O_A1 0             // 16 x 264 x 2 = 8448 -> pad 8960
#define O_HE 8960          // 16 x 520 x 2 = 16640 -> pad 16896
#define O_QB 25856         // 512 f32
#define O_BE2 27904        // 1024 f32
#define ENC_SMEM 32768

__global__ void __launch_bounds__(512, 1)
encoder_kernel(const float* __restrict__ cand,
               const float* __restrict__ be1,
               const float* __restrict__ be2,
               const float* __restrict__ eps,
               float* __restrict__ out) {
    extern __shared__ char esm[];
    __half* A1  = reinterpret_cast<__half*>(esm + O_A1);
    __half* HE  = reinterpret_cast<__half*>(esm + O_HE);
    float* qb1  = reinterpret_cast<float*>(esm + O_QB);
    float* be2s = reinterpret_cast<float*>(esm + O_BE2);
    __shared__ int idxs[16];
    __shared__ float redp[16];

    const int tid = threadIdx.x;
    const int b = blockIdx.y;
    const int bx = blockIdx.x;              // M-quarter: rows bx*16..+15
    const int w = tid >> 5, lane = tid & 31;
    const int wn = w;                       // 0..15

    if (tid < 16) {
        int gr = bx * 16 + tid;
        idxs[tid] = (gr < 50) ? g_topk[b * SK + gr] : -1;
    }
    qb1[tid]  = g_qWe1[b * EH + tid] + be1[tid];
    be2s[tid]       = be2[tid];
    be2s[tid + 512] = be2[tid + 512];
    __syncthreads();

    // gather 16 selected rows -> A1 fp16 (invalid rows zero)
    #pragma unroll
    for (int t = 0; t < 2; t++) {
        int idx = tid + t * 512;            // 0..1023
        int r = idx >> 6, k4 = idx & 63;
        uint2 u; u.x = 0u; u.y = 0u;
        int ci = idxs[r];
        if (ci >= 0) {
            float4 v = *reinterpret_cast<const float4*>(
                &cand[((size_t)b * KK + ci) * DC + k4 * 4]);
            u.x = h2u(__floats2half2_rn(v.x, v.y));
            u.y = h2u(__floats2half2_rn(v.z, v.w));
        }
        *reinterpret_cast<uint2*>(&A1[r * EST + k4 * 4]) = u;
    }
    __syncthreads();

    // ---- GEMM1: 16 rows x 512 cols; warp wn covers cols wn*32..+31 ----
    {
        float acc[4][4];
        #pragma unroll
        for (int nt = 0; nt < 4; nt++)
            #pragma unroll
            for (int r = 0; r < 4; r++) acc[nt][r] = 0.f;

        #pragma unroll 4
        for (int kt = 0; kt < 16; kt++) {
            int c = kt >> 1, ktile = kt & 1;
            uint4 a = ldsA(A1, EST, 0, kt * 16, lane);
            #pragma unroll
            for (int nt = 0; nt < 4; nt++) {
                int ntl = wn * 4 + nt;
                uint2 bb = ldgB(g_We1p, (c * 64 + ntl) * 2 + ktile, lane);
                mma16(acc[nt], a, bb.x, bb.y);
            }
        }
        // epilogue -> HE fp16 (16 rows)
        #pragma unroll
        for (int nt = 0; nt < 4; nt++)
            #pragma unroll
            for (int pp = 0; pp < 2; pp++) {
                int col = wn * 32 + nt * 8 + (lane & 3) * 2;
                int row = (lane >> 2) + 8 * pp;
                float v0 = fmaxf(acc[nt][2 * pp]     + qb1[col],     0.f);
                float v1 = fmaxf(acc[nt][2 * pp + 1] + qb1[col + 1], 0.f);
                *reinterpret_cast<uint32_t*>(&HE[row * HST + col]) =
                    h2u(__floats2half2_rn(v0, v1));
            }
    }
    __syncthreads();   // HE exchange across warps

    // ---- GEMM2: 16 rows x 1024 interleaved cols; warp wn covers ntl wn*8..+7 ----
    float acc2[8][4];
    #pragma unroll
    for (int nt = 0; nt < 8; nt++)
        #pragma unroll
        for (int r = 0; r < 4; r++) acc2[nt][r] = 0.f;

    #pragma unroll 4
    for (int kt = 0; kt < 32; kt++) {
        int c = kt >> 1, ktile = kt & 1;
        uint4 a = ldsA(HE, HST, 0, kt * 16, lane);
        #pragma unroll
        for (int nt = 0; nt < 8; nt++) {
            int ntl = wn * 8 + nt;
            uint2 bb = ldgB(g_We2p, (c * 128 + ntl) * 2 + ktile, lane);
            mma16(acc2[nt], a, bb.x, bb.y);
        }
    }

    // epilogue: (mu, ls) pairs -> z, kl
    float kl = 0.f;
    #pragma unroll
    for (int nt = 0; nt < 8; nt++)
        #pragma unroll
        for (int pp = 0; pp < 2; pp++) {
            int j = (wn * 8 + nt) * 4 + (lane & 3);
            int row = bx * 16 + (lane >> 2) + 8 * pp;
            if (row < 50) {
                float mu  = acc2[nt][2 * pp]     + be2s[j];
                float lsr = acc2[nt][2 * pp + 1] + be2s[512 + j];
                float lsc = fminf(fmaxf(lsr, -10.f), 10.f);
                float sd = expf(lsc);
                size_t grow = (size_t)b * SK + row;
                out[OFF_Z + grow * IB + j] = mu + sd * eps[grow * IB + j];
                kl += mu * mu + sd * sd - 1.0f - 2.0f * lsr;
            }
        }
    #pragma unroll
    for (int off = 16; off; off >>= 1) kl += __shfl_down_sync(0xffffffffu, kl, off);
    if (lane == 0) redp[w] = kl;
    __syncthreads();
    if (tid == 0) {
        float s = 0.f;
        #pragma unroll
        for (int ww = 0; ww < 16; ww++) s += redp[ww];
        atomicAdd(&out[OFF_KL], 0.5f * s * (0.001f / (float)(BB * SK)));
    }
}

// ===================== launch =====================
extern "C" void kernel_launch(void* const* d_in, const int* in_sizes, int n_in,
                              void* d_out, int out_size) {
    const float* query = (const float*)d_in[0];
    const float* cand  = (const float*)d_in[1];
    const float* score = (const float*)d_in[2];
    const float* gum   = (const float*)d_in[3];
    const float* eps   = (const float*)d_in[4];
    const float* W1    = (const float*)d_in[5];
    const float* b1    = (const float*)d_in[6];
    const float* W2    = (const float*)d_in[7];
    const float* b2    = (const float*)d_in[8];
    const float* We1   = (const float*)d_in[9];
    const float* be1   = (const float*)d_in[10];
    const float* We2   = (const float*)d_in[11];
    const float* be2   = (const float*)d_in[12];
    float* out = (float*)d_out;

    static int attr_set = 0;
    if (!attr_set) {
        cudaFuncSetAttribute(logits_mma_kernel,
                             cudaFuncAttributeMaxDynamicSharedMemorySize, SM_DYN);
        cudaFuncSetAttribute(encoder_kernel,
                             cudaFuncAttributeMaxDynamicSharedMemorySize, ENC_SMEM);
        attr_set = 1;
    }

    prep_kernel<<<256 + 96, 256>>>(W1, query, We1);
    logits_mma_kernel<<<dim3(KK / 64, BB), 256, SM_DYN>>>(cand, b1, W2, b2, gum,
                                                          We1, We2, out);
    topk_kernel<<<BB, 1024>>>(score, out);
    encoder_kernel<<<dim3(4, BB), 512, ENC_SMEM>>>(cand, be1, be2, eps, out);
}